// round 1
// baseline (speedup 1.0000x reference)
#include <cuda_runtime.h>
#include <math.h>

// ---------------- configuration ----------------
#define THREADS 256
#define RPT 8              // rows per thread
#define RB (THREADS * RPT) // rows per block = 2048
#define CTILE 512          // columns per block tile
#define MAXP 16384         // capacity for point counts (actual 12288)

// ---------------- device scratch (no allocations allowed) ----------------
__device__ unsigned g_key[2][MAXP];   // order-preserving max-score keys
__device__ float    g_partial[2][128];

// ---------------- packed f32x2 helpers ----------------
typedef unsigned long long ull;

__device__ __forceinline__ ull pack2(float x, float y) {
    ull r;
    asm("mov.b64 %0, {%1, %2};" : "=l"(r) : "f"(x), "f"(y));
    return r;
}
__device__ __forceinline__ void unpack2(ull v, float& x, float& y) {
    asm("mov.b64 {%0, %1}, %2;" : "=f"(x), "=f"(y) : "l"(v));
}
__device__ __forceinline__ ull fma2(ull a, ull b, ull c) {
    ull d;
    asm("fma.rn.f32x2 %0, %1, %2, %3;" : "=l"(d) : "l"(a), "l"(b), "l"(c));
    return d;
}

// ---------------- kernel 0: init keys ----------------
__global__ void k_init(int n0, int n1) {
    int i = blockIdx.x * blockDim.x + threadIdx.x;
    if (i < n0) g_key[0][i] = 0u;  // decodes to most-negative; always overwritten
    if (i < n1) g_key[1][i] = 0u;
}

// ---------------- kernel 1: pairwise max-score ----------------
// dir 0: rows = true_pos (NA=N), cols = pred_pos (NB=M)  -> per-true nearest (mins)
// dir 1: rows = pred_pos (NA=M), cols = true_pos (NB=N)  -> per-pred nearest (mins_seeds)
__global__ void k_pairs(const float* __restrict__ tp, const float* __restrict__ pp,
                        int N, int M) {
    const int dir = blockIdx.z;
    const float* __restrict__ A = dir ? pp : tp;
    const float* __restrict__ B = dir ? tp : pp;
    const int NA = dir ? M : N;
    const int NB = dir ? N : M;

    __shared__ __align__(16) float sbx[CTILE];
    __shared__ __align__(16) float sby[CTILE];
    __shared__ __align__(16) float sbz[CTILE];
    __shared__ __align__(16) float snh[CTILE];

    const int tid = threadIdx.x;
    const int rbase = blockIdx.x * RB;
    if (rbase >= NA) return;  // whole block out of range for this direction

    // ---- stage column tile: bx, by, bz, nh = -0.5*|b|^2 ----
    const int cbase = blockIdx.y * CTILE;
    for (int c = tid; c < CTILE; c += THREADS) {
        int col = cbase + c;
        float bx = 0.f, by = 0.f, bz = 0.f, nh = -1e30f;  // pad: never wins the max
        if (col < NB) {
            bx = B[3 * col + 0];
            by = B[3 * col + 1];
            bz = B[3 * col + 2];
            nh = -0.5f * (bx * bx + by * by + bz * bz);
        }
        sbx[c] = bx; sby[c] = by; sbz[c] = bz; snh[c] = nh;
    }
    __syncthreads();

    // ---- load this thread's rows, duplicated into both packed lanes ----
    ull axx[RPT], ayy[RPT], azz[RPT];
    bool valid[RPT];
    #pragma unroll
    for (int r = 0; r < RPT; r++) {
        int row = rbase + r * THREADS + tid;
        valid[r] = (row < NA);
        int rr = valid[r] ? row : 0;
        float ax = A[3 * rr + 0];
        float ay = A[3 * rr + 1];
        float az = A[3 * rr + 2];
        axx[r] = pack2(ax, ax);
        ayy[r] = pack2(ay, ay);
        azz[r] = pack2(az, az);
    }

    float m0[RPT], m1[RPT];
    #pragma unroll
    for (int r = 0; r < RPT; r++) { m0[r] = -1e30f; m1[r] = -1e30f; }

    const float2* __restrict__ px = reinterpret_cast<const float2*>(sbx);
    const float2* __restrict__ py = reinterpret_cast<const float2*>(sby);
    const float2* __restrict__ pz = reinterpret_cast<const float2*>(sbz);
    const float2* __restrict__ ph = reinterpret_cast<const float2*>(snh);

    // ---- main loop: 2 columns per iteration, 8 rows per thread ----
    #pragma unroll 4
    for (int j = 0; j < CTILE / 2; j++) {
        float2 fx = px[j];  // warp-uniform index -> LDS broadcast, conflict-free
        float2 fy = py[j];
        float2 fz = pz[j];
        float2 fh = ph[j];
        ull bxx = pack2(fx.x, fx.y);
        ull byy = pack2(fy.x, fy.y);
        ull bzz = pack2(fz.x, fz.y);
        ull nh2 = pack2(fh.x, fh.y);
        #pragma unroll
        for (int r = 0; r < RPT; r++) {
            ull t = fma2(axx[r], bxx, nh2);
            t = fma2(ayy[r], byy, t);
            t = fma2(azz[r], bzz, t);   // t = a.b - 0.5*|b|^2 (both lanes)
            float lo, hi;
            unpack2(t, lo, hi);
            m0[r] = fmaxf(m0[r], lo);
            m1[r] = fmaxf(m1[r], hi);
        }
    }

    // ---- fold to global per-row max via order-preserving uint atomicMax ----
    #pragma unroll
    for (int r = 0; r < RPT; r++) {
        if (!valid[r]) continue;
        int row = rbase + r * THREADS + tid;
        float mx = fmaxf(m0[r], m1[r]);
        unsigned bits = __float_as_uint(mx);
        unsigned key = bits ^ ((bits & 0x80000000u) ? 0xFFFFFFFFu : 0x80000000u);
        atomicMax(&g_key[dir][row], key);
    }
}

// ---------------- kernel 2: decode + distances + partial sums ----------------
__global__ void k_final(const float* __restrict__ tp, const float* __restrict__ pp,
                        int N, int M, float* __restrict__ out) {
    const int dir = blockIdx.y;
    const float* __restrict__ A = dir ? pp : tp;
    const int NA = dir ? M : N;
    const int i = blockIdx.x * THREADS + threadIdx.x;

    float dist = 0.f;
    if (i < NA) {
        unsigned u = g_key[dir][i];
        unsigned bits = (u & 0x80000000u) ? (u ^ 0x80000000u) : ~u;
        float score = __uint_as_float(bits);
        float ax = A[3 * i + 0];
        float ay = A[3 * i + 1];
        float az = A[3 * i + 2];
        float sa = ax * ax + ay * ay + az * az;
        float d2 = fmaxf(sa - 2.0f * score, 0.0f);
        dist = sqrtf(d2);
        if (dir == 1) out[1 + i] = dist;  // mins_seeds
    }

    __shared__ float red[THREADS];
    red[threadIdx.x] = dist;
    __syncthreads();
    for (int s = THREADS / 2; s > 0; s >>= 1) {
        if (threadIdx.x < s) red[threadIdx.x] += red[threadIdx.x + s];
        __syncthreads();
    }
    if (threadIdx.x == 0) g_partial[dir][blockIdx.x] = red[0];
}

// ---------------- kernel 3: deterministic final sums + scalars ----------------
__global__ void k_out(int N, int M, int nb0, int nb1, float* __restrict__ out) {
    if (threadIdx.x == 0) {
        float s0 = 0.f, s1 = 0.f;
        for (int i = 0; i < nb0; i++) s0 += g_partial[0][i];
        for (int i = 0; i < nb1; i++) s1 += g_partial[1][i];
        float loss = s0 / (float)N;        // mean(mins)        over true points
        float loss_seeds = s1 / (float)M;  // mean(mins_seeds)  over pred points
        out[0] = loss + loss_seeds;
        out[1 + M] = loss;
        out[2 + M] = loss_seeds;
    }
}

// ---------------- launch ----------------
extern "C" void kernel_launch(void* const* d_in, const int* in_sizes, int n_in,
                              void* d_out, int out_size) {
    const float* tp = (const float*)d_in[0];
    const float* pp = (const float*)d_in[1];
    float* out = (float*)d_out;
    const int N = in_sizes[0] / 3;
    const int M = in_sizes[1] / 3;
    const int maxP = (N > M) ? N : M;

    k_init<<<(maxP + THREADS - 1) / THREADS, THREADS>>>(N, M);

    dim3 g1((maxP + RB - 1) / RB, (maxP + CTILE - 1) / CTILE, 2);
    k_pairs<<<g1, THREADS>>>(tp, pp, N, M);

    int nb0 = (N + THREADS - 1) / THREADS;
    int nb1 = (M + THREADS - 1) / THREADS;
    dim3 g2((maxP + THREADS - 1) / THREADS, 2);
    k_final<<<g2, THREADS>>>(tp, pp, N, M, out);

    k_out<<<1, 32>>>(N, M, nb0, nb1, out);
}

// round 2
// speedup vs baseline: 1.0955x; 1.0955x over previous
#include <cuda_runtime.h>
#include <math.h>

// ---------------- configuration ----------------
#define THREADS 512
#define RPT 8               // rows per thread
#define RB (THREADS * RPT)  // rows per block = 4096
#define CTILE 512           // columns per block tile (== THREADS)
#define MAXP 16384
#define MAXCH (MAXP / CTILE)  // 32 column chunks max

// ---------------- device scratch (no allocations allowed) ----------------
// Race-free partial maxima: each (dir, colchunk) block owns its row slice.
// Fully overwritten each call -> no init kernel, no atomics.
__device__ float g_part[2][MAXCH][MAXP];
__device__ float g_bsum[2][64];

// ---------------- packed f32x2 helpers ----------------
typedef unsigned long long ull;

__device__ __forceinline__ ull pack2(float x, float y) {
    ull r;
    asm("mov.b64 %0, {%1, %2};" : "=l"(r) : "f"(x), "f"(y));
    return r;
}
__device__ __forceinline__ void unpack2(ull v, float& x, float& y) {
    asm("mov.b64 {%0, %1}, %2;" : "=f"(x), "=f"(y) : "l"(v));
}
__device__ __forceinline__ ull fma2(ull a, ull b, ull c) {
    ull d;
    asm("fma.rn.f32x2 %0, %1, %2, %3;" : "=l"(d) : "l"(a), "l"(b), "l"(c));
    return d;
}

// ---------------- kernel 1: pairwise max-score ----------------
// score = a.b - 0.5*|b|^2 ; maximizing score == minimizing distance.
// dir 0: rows = true_pos, cols = pred_pos -> mins
// dir 1: rows = pred_pos, cols = true_pos -> mins_seeds
__global__ void __launch_bounds__(THREADS, 1)
k_pairs(const float* __restrict__ tp, const float* __restrict__ pp,
        int N, int M) {
    const int dir = blockIdx.z;
    const float* __restrict__ A = dir ? pp : tp;
    const float* __restrict__ B = dir ? tp : pp;
    const int NA = dir ? M : N;
    const int NB = dir ? N : M;

    __shared__ __align__(16) float sbx[CTILE];
    __shared__ __align__(16) float sby[CTILE];
    __shared__ __align__(16) float sbz[CTILE];
    __shared__ __align__(16) float snh[CTILE];

    const int tid = threadIdx.x;
    const int rbase = blockIdx.x * RB;
    if (rbase >= NA) return;

    // ---- stage column tile: exactly one column per thread ----
    {
        int col = blockIdx.y * CTILE + tid;
        float bx = 0.f, by = 0.f, bz = 0.f, nh = -1e30f;  // pad never wins
        if (col < NB) {
            bx = B[3 * col + 0];
            by = B[3 * col + 1];
            bz = B[3 * col + 2];
            nh = -0.5f * (bx * bx + by * by + bz * bz);
        }
        sbx[tid] = bx; sby[tid] = by; sbz[tid] = bz; snh[tid] = nh;
    }
    __syncthreads();

    // ---- this thread's rows, duplicated into both packed lanes ----
    ull axx[RPT], ayy[RPT], azz[RPT];
    #pragma unroll
    for (int r = 0; r < RPT; r++) {
        int row = rbase + r * THREADS + tid;
        int rr = (row < NA) ? row : 0;
        float ax = A[3 * rr + 0];
        float ay = A[3 * rr + 1];
        float az = A[3 * rr + 2];
        axx[r] = pack2(ax, ax);
        ayy[r] = pack2(ay, ay);
        azz[r] = pack2(az, az);
    }

    float m0[RPT], m1[RPT];
    #pragma unroll
    for (int r = 0; r < RPT; r++) { m0[r] = -1e30f; m1[r] = -1e30f; }

    const float2* __restrict__ px = reinterpret_cast<const float2*>(sbx);
    const float2* __restrict__ py = reinterpret_cast<const float2*>(sby);
    const float2* __restrict__ pz = reinterpret_cast<const float2*>(sbz);
    const float2* __restrict__ ph = reinterpret_cast<const float2*>(snh);

    // ---- main loop: 2 columns x 8 rows per iteration ----
    #pragma unroll 4
    for (int j = 0; j < CTILE / 2; j++) {
        float2 fx = px[j];  // warp-uniform -> LDS broadcast, conflict-free
        float2 fy = py[j];
        float2 fz = pz[j];
        float2 fh = ph[j];
        ull bxx = pack2(fx.x, fx.y);
        ull byy = pack2(fy.x, fy.y);
        ull bzz = pack2(fz.x, fz.y);
        ull nh2 = pack2(fh.x, fh.y);
        #pragma unroll
        for (int r = 0; r < RPT; r++) {
            ull t = fma2(axx[r], bxx, nh2);
            t = fma2(ayy[r], byy, t);
            t = fma2(azz[r], bzz, t);
            float lo, hi;
            unpack2(t, lo, hi);
            m0[r] = fmaxf(m0[r], lo);
            m1[r] = fmaxf(m1[r], hi);
        }
    }

    // ---- write per-(block,chunk) partial max; coalesced, race-free ----
    #pragma unroll
    for (int r = 0; r < RPT; r++) {
        int row = rbase + r * THREADS + tid;
        if (row < NA)
            g_part[dir][blockIdx.y][row] = fmaxf(m0[r], m1[r]);
    }
}

// ---------------- kernel 2: reduce chunks, distances, block sums ----------------
#define FTHREADS 256
__global__ void k_final(const float* __restrict__ tp, const float* __restrict__ pp,
                        int N, int M, int nch, float* __restrict__ out) {
    const int dir = blockIdx.y;
    const float* __restrict__ A = dir ? pp : tp;
    const int NA = dir ? M : N;
    const int i = blockIdx.x * FTHREADS + threadIdx.x;

    float dist = 0.f;
    if (i < NA) {
        float s = -1e30f;
        for (int c = 0; c < nch; c++)
            s = fmaxf(s, g_part[dir][c][i]);
        float ax = A[3 * i + 0];
        float ay = A[3 * i + 1];
        float az = A[3 * i + 2];
        float sa = ax * ax + ay * ay + az * az;
        dist = sqrtf(fmaxf(sa - 2.0f * s, 0.0f));
        if (dir == 1) out[1 + i] = dist;  // mins_seeds
    }

    __shared__ float red[FTHREADS];
    red[threadIdx.x] = dist;
    __syncthreads();
    for (int s = FTHREADS / 2; s > 0; s >>= 1) {
        if (threadIdx.x < s) red[threadIdx.x] += red[threadIdx.x + s];
        __syncthreads();
    }
    if (threadIdx.x == 0) g_bsum[dir][blockIdx.x] = red[0];
}

// ---------------- kernel 3: parallel final sums + scalars ----------------
__global__ void k_out(int N, int M, int nb, float* __restrict__ out) {
    __shared__ float s[128];
    int t = threadIdx.x;  // blockDim = 64
    s[t]      = (t < nb) ? g_bsum[0][t] : 0.f;
    s[64 + t] = (t < nb) ? g_bsum[1][t] : 0.f;
    __syncthreads();
    #pragma unroll
    for (int st = 32; st > 0; st >>= 1) {
        if (t < st) {
            s[t] += s[t + st];
            s[64 + t] += s[64 + t + st];
        }
        __syncthreads();
    }
    if (t == 0) {
        float loss = s[0] / (float)N;         // mean(mins)
        float loss_seeds = s[64] / (float)M;  // mean(mins_seeds)
        out[0] = loss + loss_seeds;
        out[1 + M] = loss;
        out[2 + M] = loss_seeds;
    }
}

// ---------------- launch ----------------
extern "C" void kernel_launch(void* const* d_in, const int* in_sizes, int n_in,
                              void* d_out, int out_size) {
    const float* tp = (const float*)d_in[0];
    const float* pp = (const float*)d_in[1];
    float* out = (float*)d_out;
    const int N = in_sizes[0] / 3;
    const int M = in_sizes[1] / 3;
    const int maxP = (N > M) ? N : M;

    const int nch = (maxP + CTILE - 1) / CTILE;          // column chunks
    dim3 g1((maxP + RB - 1) / RB, nch, 2);               // (3, 24, 2) = 144 blocks
    k_pairs<<<g1, THREADS>>>(tp, pp, N, M);

    const int nb = (maxP + FTHREADS - 1) / FTHREADS;     // 48
    dim3 g2(nb, 2);
    k_final<<<g2, FTHREADS>>>(tp, pp, N, M, nch, out);

    k_out<<<1, 64>>>(N, M, nb, out);
}